// round 1
// baseline (speedup 1.0000x reference)
#include <cuda_runtime.h>
#include <cuda_bf16.h>
#include <cstdint>

// Problem constants (fixed by dataset)
#define NMAX   20000
#define EMAX   320000
#define DIN    512
#define DH     256
#define NGR    128

// ---------------- scratch (static device globals; no runtime alloc) ----------
__device__ int   g_deg[NMAX];
__device__ int   g_rowstart[NMAX + 1];
__device__ int   g_cursor[NMAX];
__device__ int   g_csr[EMAX];
__device__ float g_dinv[NMAX];
__device__ float g_y[(size_t)NMAX * DH];   // gemm output (pre-aggregate), reused for layer 2
__device__ float g_h[(size_t)NMAX * DH];   // layer-1 hidden
__device__ float g_gsum[NGR];
__device__ int   g_cnt[NGR];

// ---------------- small utility kernels --------------------------------------
__global__ void zero_kernel(int n) {
    int i = blockIdx.x * blockDim.x + threadIdx.x;
    if (i < n) g_deg[i] = 0;
    if (i < NGR) { g_gsum[i] = 0.0f; g_cnt[i] = 0; }
}

// histogram of in-degrees (dst row of edge_index) + per-graph node counts
__global__ void hist_kernel(const int* __restrict__ ei, const int* __restrict__ batch,
                            int n, int e) {
    int i = blockIdx.x * blockDim.x + threadIdx.x;
    if (i < e) atomicAdd(&g_deg[ei[e + i]], 1);
    if (i < n) atomicAdd(&g_cnt[batch[i]], 1);
}

// single-block exclusive scan of g_deg -> g_rowstart / g_cursor, plus dinv
__global__ void scan_kernel(int n) {
    __shared__ int wsum[32];
    int tid = threadIdx.x;
    int lane = tid & 31, wid = tid >> 5;
    int run = 0;
    int nchunks = (n + 1023) / 1024;
    for (int c = 0; c < nchunks; ++c) {
        int i = c * 1024 + tid;
        int v = (i < n) ? g_deg[i] : 0;
        // warp inclusive scan
        int x = v;
        #pragma unroll
        for (int off = 1; off < 32; off <<= 1) {
            int t = __shfl_up_sync(0xffffffffu, x, off);
            if (lane >= off) x += t;
        }
        if (lane == 31) wsum[wid] = x;
        __syncthreads();
        if (wid == 0) {
            int s = wsum[lane];
            #pragma unroll
            for (int off = 1; off < 32; off <<= 1) {
                int t = __shfl_up_sync(0xffffffffu, s, off);
                if (lane >= off) s += t;
            }
            wsum[lane] = s;
        }
        __syncthreads();
        int woff = (wid > 0) ? wsum[wid - 1] : 0;
        int incl = x + woff;
        int total = wsum[31];
        if (i < n) {
            int excl = run + incl - v;
            g_rowstart[i] = excl;
            g_cursor[i]   = excl;
            g_dinv[i]     = rsqrtf((float)(v + 1));   // +1 self-loop
        }
        run += total;
        __syncthreads();
    }
    if (tid == 0) g_rowstart[n] = run;
}

__global__ void fill_kernel(const int* __restrict__ ei, int e) {
    int i = blockIdx.x * blockDim.x + threadIdx.x;
    if (i < e) {
        int s = ei[i];
        int d = ei[e + i];
        int p = atomicAdd(&g_cursor[d], 1);
        g_csr[p] = s;
    }
}

// ---------------- tf32 tensor-core GEMM:  Y[m,:] = scale[m] * (A[m,:] @ B) ----
__device__ __forceinline__ uint32_t f2tf(float f) {
    uint32_t r;
    asm("cvt.rna.tf32.f32 %0, %1;" : "=r"(r) : "f"(f));
    return r;
}

__device__ __forceinline__ void mma_tf32(float* c, const uint32_t* a, const uint32_t* b) {
    asm volatile(
        "mma.sync.aligned.m16n8k8.row.col.f32.tf32.tf32.f32 "
        "{%0,%1,%2,%3}, {%4,%5,%6,%7}, {%8,%9}, {%0,%1,%2,%3};\n"
        : "+f"(c[0]), "+f"(c[1]), "+f"(c[2]), "+f"(c[3])
        : "r"(a[0]), "r"(a[1]), "r"(a[2]), "r"(a[3]),
          "r"(b[0]), "r"(b[1]));
}

#define BM 128
#define BN 64
#define BKT 32
// 256 threads = 8 warps in a 4(M) x 2(N) grid, each warp computes 32x32.
__global__ __launch_bounds__(256)
void gemm_tf32_scaled(const float* __restrict__ A, const float* __restrict__ B,
                      const float* __restrict__ scale, float* __restrict__ Y,
                      int M, int K) {
    __shared__ uint32_t As[BM][36];  // padded: 4*gid+tig -> conflict-free frag loads
    __shared__ uint32_t Bs[BKT][72]; // padded: 8*tig+gid -> conflict-free frag loads

    int tid  = threadIdx.x;
    int lane = tid & 31, warp = tid >> 5;
    int wm = warp >> 1, wn = warp & 1;
    int gid = lane >> 2, tig = lane & 3;
    int m0 = blockIdx.x * BM;
    int n0 = blockIdx.y * BN;

    float c[2][4][4] = {};

    for (int k0 = 0; k0 < K; k0 += BKT) {
        // A tile: 128x32 floats = 1024 float4, 4 per thread
        #pragma unroll
        for (int t = 0; t < 4; ++t) {
            int f4 = tid + t * 256;
            int r = f4 >> 3, cc = (f4 & 7) << 2;
            int gr = m0 + r;
            float4 v = make_float4(0.f, 0.f, 0.f, 0.f);
            if (gr < M) v = *(const float4*)(A + (size_t)gr * K + k0 + cc);
            As[r][cc + 0] = f2tf(v.x);
            As[r][cc + 1] = f2tf(v.y);
            As[r][cc + 2] = f2tf(v.z);
            As[r][cc + 3] = f2tf(v.w);
        }
        // B tile: 32x64 floats = 512 float4, 2 per thread
        #pragma unroll
        for (int t = 0; t < 2; ++t) {
            int f4 = tid + t * 256;
            int r = f4 >> 4, cc = (f4 & 15) << 2;
            float4 v = *(const float4*)(B + (size_t)(k0 + r) * DH + n0 + cc);
            Bs[r][cc + 0] = f2tf(v.x);
            Bs[r][cc + 1] = f2tf(v.y);
            Bs[r][cc + 2] = f2tf(v.z);
            Bs[r][cc + 3] = f2tf(v.w);
        }
        __syncthreads();

        #pragma unroll
        for (int kk = 0; kk < BKT; kk += 8) {
            uint32_t a[2][4], b[4][2];
            #pragma unroll
            for (int i = 0; i < 2; ++i) {
                int mrow = wm * 32 + i * 16;
                a[i][0] = As[mrow + gid][kk + tig];
                a[i][1] = As[mrow + gid + 8][kk + tig];
                a[i][2] = As[mrow + gid][kk + tig + 4];
                a[i][3] = As[mrow + gid + 8][kk + tig + 4];
            }
            #pragma unroll
            for (int j = 0; j < 4; ++j) {
                int ncol = wn * 32 + j * 8 + gid;
                b[j][0] = Bs[kk + tig][ncol];
                b[j][1] = Bs[kk + tig + 4][ncol];
            }
            #pragma unroll
            for (int i = 0; i < 2; ++i)
                #pragma unroll
                for (int j = 0; j < 4; ++j)
                    mma_tf32(c[i][j], a[i], b[j]);
        }
        __syncthreads();
    }

    // epilogue: scale rows by dinv[m]
    #pragma unroll
    for (int i = 0; i < 2; ++i) {
        int r0 = m0 + wm * 32 + i * 16 + gid;
        int r1 = r0 + 8;
        float s0 = (r0 < M) ? scale[r0] : 0.f;
        float s1 = (r1 < M) ? scale[r1] : 0.f;
        #pragma unroll
        for (int j = 0; j < 4; ++j) {
            int cb = n0 + wn * 32 + j * 8 + tig * 2;
            if (r0 < M) {
                Y[(size_t)r0 * DH + cb]     = s0 * c[i][j][0];
                Y[(size_t)r0 * DH + cb + 1] = s0 * c[i][j][1];
            }
            if (r1 < M) {
                Y[(size_t)r1 * DH + cb]     = s1 * c[i][j][2];
                Y[(size_t)r1 * DH + cb + 1] = s1 * c[i][j][3];
            }
        }
    }
}

// ---------------- warp-per-node gather aggregation ----------------------------
// out[node,:] = relu( dinv[node] * (sum_{src in in(node)} y[src,:] + y[node,:]) + bias )
__global__ __launch_bounds__(256)
void aggregate1_kernel(const float* __restrict__ y, const float* __restrict__ bias,
                       float* __restrict__ out, int n) {
    int gw   = (blockIdx.x * blockDim.x + threadIdx.x) >> 5;
    int lane = threadIdx.x & 31;
    if (gw >= n) return;
    int e0 = g_rowstart[gw], e1 = g_rowstart[gw + 1];

    float4 a0 = make_float4(0.f, 0.f, 0.f, 0.f);
    float4 a1 = make_float4(0.f, 0.f, 0.f, 0.f);

    int e = e0;
    for (; e + 4 <= e1; e += 4) {
        int s0 = g_csr[e], s1 = g_csr[e + 1], s2 = g_csr[e + 2], s3 = g_csr[e + 3];
        const float4* p0 = (const float4*)(y + (size_t)s0 * DH) + lane;
        const float4* p1 = (const float4*)(y + (size_t)s1 * DH) + lane;
        const float4* p2 = (const float4*)(y + (size_t)s2 * DH) + lane;
        const float4* p3 = (const float4*)(y + (size_t)s3 * DH) + lane;
        float4 u0 = p0[0], w0 = p0[32];
        float4 u1 = p1[0], w1 = p1[32];
        float4 u2 = p2[0], w2 = p2[32];
        float4 u3 = p3[0], w3 = p3[32];
        a0.x += u0.x + u1.x + u2.x + u3.x;  a0.y += u0.y + u1.y + u2.y + u3.y;
        a0.z += u0.z + u1.z + u2.z + u3.z;  a0.w += u0.w + u1.w + u2.w + u3.w;
        a1.x += w0.x + w1.x + w2.x + w3.x;  a1.y += w0.y + w1.y + w2.y + w3.y;
        a1.z += w0.z + w1.z + w2.z + w3.z;  a1.w += w0.w + w1.w + w2.w + w3.w;
    }
    for (; e < e1; ++e) {
        int s = g_csr[e];
        const float4* p = (const float4*)(y + (size_t)s * DH) + lane;
        float4 u = p[0], w = p[32];
        a0.x += u.x; a0.y += u.y; a0.z += u.z; a0.w += u.w;
        a1.x += w.x; a1.y += w.y; a1.z += w.z; a1.w += w.w;
    }
    // self loop
    {
        const float4* p = (const float4*)(y + (size_t)gw * DH) + lane;
        float4 u = p[0], w = p[32];
        a0.x += u.x; a0.y += u.y; a0.z += u.z; a0.w += u.w;
        a1.x += w.x; a1.y += w.y; a1.z += w.z; a1.w += w.w;
    }
    float dv = g_dinv[gw];
    float4 b0 = ((const float4*)bias)[lane];
    float4 b1 = ((const float4*)bias)[32 + lane];
    float4 r0, r1;
    r0.x = fmaxf(dv * a0.x + b0.x, 0.f); r0.y = fmaxf(dv * a0.y + b0.y, 0.f);
    r0.z = fmaxf(dv * a0.z + b0.z, 0.f); r0.w = fmaxf(dv * a0.w + b0.w, 0.f);
    r1.x = fmaxf(dv * a1.x + b1.x, 0.f); r1.y = fmaxf(dv * a1.y + b1.y, 0.f);
    r1.z = fmaxf(dv * a1.z + b1.z, 0.f); r1.w = fmaxf(dv * a1.w + b1.w, 0.f);
    float4* op = (float4*)(out + (size_t)gw * DH) + lane;
    op[0]  = r0;
    op[32] = r1;
}

// layer-2 aggregate fused with pool+FC: never materializes h2.
__global__ __launch_bounds__(256)
void aggregate2_pool_kernel(const float* __restrict__ y, const float* __restrict__ bias,
                            const float* __restrict__ wfc, const int* __restrict__ batch,
                            int n) {
    int gw   = (blockIdx.x * blockDim.x + threadIdx.x) >> 5;
    int lane = threadIdx.x & 31;
    if (gw >= n) return;
    int e0 = g_rowstart[gw], e1 = g_rowstart[gw + 1];

    float4 a0 = make_float4(0.f, 0.f, 0.f, 0.f);
    float4 a1 = make_float4(0.f, 0.f, 0.f, 0.f);

    int e = e0;
    for (; e + 4 <= e1; e += 4) {
        int s0 = g_csr[e], s1 = g_csr[e + 1], s2 = g_csr[e + 2], s3 = g_csr[e + 3];
        const float4* p0 = (const float4*)(y + (size_t)s0 * DH) + lane;
        const float4* p1 = (const float4*)(y + (size_t)s1 * DH) + lane;
        const float4* p2 = (const float4*)(y + (size_t)s2 * DH) + lane;
        const float4* p3 = (const float4*)(y + (size_t)s3 * DH) + lane;
        float4 u0 = p0[0], w0 = p0[32];
        float4 u1 = p1[0], w1 = p1[32];
        float4 u2 = p2[0], w2 = p2[32];
        float4 u3 = p3[0], w3 = p3[32];
        a0.x += u0.x + u1.x + u2.x + u3.x;  a0.y += u0.y + u1.y + u2.y + u3.y;
        a0.z += u0.z + u1.z + u2.z + u3.z;  a0.w += u0.w + u1.w + u2.w + u3.w;
        a1.x += w0.x + w1.x + w2.x + w3.x;  a1.y += w0.y + w1.y + w2.y + w3.y;
        a1.z += w0.z + w1.z + w2.z + w3.z;  a1.w += w0.w + w1.w + w2.w + w3.w;
    }
    for (; e < e1; ++e) {
        int s = g_csr[e];
        const float4* p = (const float4*)(y + (size_t)s * DH) + lane;
        float4 u = p[0], w = p[32];
        a0.x += u.x; a0.y += u.y; a0.z += u.z; a0.w += u.w;
        a1.x += w.x; a1.y += w.y; a1.z += w.z; a1.w += w.w;
    }
    {
        const float4* p = (const float4*)(y + (size_t)gw * DH) + lane;
        float4 u = p[0], w = p[32];
        a0.x += u.x; a0.y += u.y; a0.z += u.z; a0.w += u.w;
        a1.x += w.x; a1.y += w.y; a1.z += w.z; a1.w += w.w;
    }
    float dv = g_dinv[gw];
    float4 b0 = ((const float4*)bias)[lane];
    float4 b1 = ((const float4*)bias)[32 + lane];
    float4 f0 = ((const float4*)wfc)[lane];
    float4 f1 = ((const float4*)wfc)[32 + lane];

    float h;
    float dot = 0.f;
    h = fmaxf(dv * a0.x + b0.x, 0.f); dot += h * f0.x;
    h = fmaxf(dv * a0.y + b0.y, 0.f); dot += h * f0.y;
    h = fmaxf(dv * a0.z + b0.z, 0.f); dot += h * f0.z;
    h = fmaxf(dv * a0.w + b0.w, 0.f); dot += h * f0.w;
    h = fmaxf(dv * a1.x + b1.x, 0.f); dot += h * f1.x;
    h = fmaxf(dv * a1.y + b1.y, 0.f); dot += h * f1.y;
    h = fmaxf(dv * a1.z + b1.z, 0.f); dot += h * f1.z;
    h = fmaxf(dv * a1.w + b1.w, 0.f); dot += h * f1.w;

    #pragma unroll
    for (int off = 16; off > 0; off >>= 1)
        dot += __shfl_xor_sync(0xffffffffu, dot, off);
    if (lane == 0)
        atomicAdd(&g_gsum[batch[gw]], dot);
}

__global__ void finalize_kernel(float* __restrict__ out, const float* __restrict__ bfc) {
    int g = threadIdx.x;
    if (g < NGR)
        out[g] = g_gsum[g] / fmaxf((float)g_cnt[g], 1.0f) + bfc[0];
}

// ---------------- launch ------------------------------------------------------
extern "C" void kernel_launch(void* const* d_in, const int* in_sizes, int n_in,
                              void* d_out, int out_size) {
    const float* x     = (const float*)d_in[0];
    const int*   ei    = (const int*)  d_in[1];
    const int*   batch = (const int*)  d_in[2];
    const float* W1    = (const float*)d_in[3];
    const float* b1    = (const float*)d_in[4];
    const float* W2    = (const float*)d_in[5];
    const float* b2    = (const float*)d_in[6];
    const float* wfc   = (const float*)d_in[7];
    const float* bfc   = (const float*)d_in[8];
    float* out = (float*)d_out;

    int n = in_sizes[0] / DIN;   // 20000
    int e = in_sizes[1] / 2;     // 320000

    float* yptr = nullptr;
    float* hptr = nullptr;
    cudaGetSymbolAddress((void**)&yptr, g_y);
    cudaGetSymbolAddress((void**)&hptr, g_h);

    int tz = (n + 255) / 256;
    zero_kernel<<<tz, 256>>>(n);

    int th = (e + 255) / 256;
    hist_kernel<<<th, 256>>>(ei, batch, n, e);

    scan_kernel<<<1, 1024>>>(n);

    fill_kernel<<<th, 256>>>(ei, e);

    float* dinvptr = nullptr;
    cudaGetSymbolAddress((void**)&dinvptr, g_dinv);

    dim3 ggrid((n + BM - 1) / BM, DH / BN);
    gemm_tf32_scaled<<<ggrid, 256>>>(x, W1, dinvptr, yptr, n, DIN);

    int ta = ((n * 32) + 255) / 256;
    aggregate1_kernel<<<ta, 256>>>(yptr, b1, hptr, n);

    gemm_tf32_scaled<<<ggrid, 256>>>(hptr, W2, dinvptr, yptr, n, DH);

    aggregate2_pool_kernel<<<ta, 256>>>(yptr, b2, wfc, batch, n);

    finalize_kernel<<<1, NGR>>>(out, bfc);
}

// round 2
// speedup vs baseline: 1.0022x; 1.0022x over previous
#include <cuda_runtime.h>
#include <cuda_bf16.h>
#include <cstdint>

// Problem constants (fixed by dataset)
#define NMAX   20000
#define EMAX   320000
#define DIN    512
#define DH     256
#define NGR    128

// ---------------- scratch (static device globals; no runtime alloc) ----------
__device__ int   g_deg[NMAX];
__device__ int   g_rowstart[NMAX + 1];
__device__ int   g_cursor[NMAX];
__device__ int   g_csr[EMAX];
__device__ float g_dinv[NMAX];
__device__ float g_y[(size_t)NMAX * DH];   // gemm output (pre-aggregate), reused for layer 2
__device__ float g_h[(size_t)NMAX * DH];   // layer-1 hidden
__device__ float g_gsum[NGR];
__device__ int   g_cnt[NGR];

// ---------------- small utility kernels --------------------------------------
__global__ void zero_kernel(int n) {
    int i = blockIdx.x * blockDim.x + threadIdx.x;
    if (i < n) g_deg[i] = 0;
    if (i < NGR) { g_gsum[i] = 0.0f; g_cnt[i] = 0; }
}

// histogram of in-degrees (dst row of edge_index) + per-graph node counts
__global__ void hist_kernel(const int* __restrict__ ei, const int* __restrict__ batch,
                            int n, int e) {
    int i = blockIdx.x * blockDim.x + threadIdx.x;
    if (i < e) atomicAdd(&g_deg[ei[e + i]], 1);
    if (i < n) atomicAdd(&g_cnt[batch[i]], 1);
}

// single-block exclusive scan of g_deg -> g_rowstart / g_cursor, plus dinv
__global__ void scan_kernel(int n) {
    __shared__ int wsum[32];
    int tid = threadIdx.x;
    int lane = tid & 31, wid = tid >> 5;
    int run = 0;
    int nchunks = (n + 1023) / 1024;
    for (int c = 0; c < nchunks; ++c) {
        int i = c * 1024 + tid;
        int v = (i < n) ? g_deg[i] : 0;
        // warp inclusive scan
        int x = v;
        #pragma unroll
        for (int off = 1; off < 32; off <<= 1) {
            int t = __shfl_up_sync(0xffffffffu, x, off);
            if (lane >= off) x += t;
        }
        if (lane == 31) wsum[wid] = x;
        __syncthreads();
        if (wid == 0) {
            int s = wsum[lane];
            #pragma unroll
            for (int off = 1; off < 32; off <<= 1) {
                int t = __shfl_up_sync(0xffffffffu, s, off);
                if (lane >= off) s += t;
            }
            wsum[lane] = s;
        }
        __syncthreads();
        int woff = (wid > 0) ? wsum[wid - 1] : 0;
        int incl = x + woff;
        int total = wsum[31];
        if (i < n) {
            int excl = run + incl - v;
            g_rowstart[i] = excl;
            g_cursor[i]   = excl;
            g_dinv[i]     = rsqrtf((float)(v + 1));   // +1 self-loop
        }
        run += total;
        __syncthreads();
    }
    if (tid == 0) g_rowstart[n] = run;
}

__global__ void fill_kernel(const int* __restrict__ ei, int e) {
    int i = blockIdx.x * blockDim.x + threadIdx.x;
    if (i < e) {
        int s = ei[i];
        int d = ei[e + i];
        int p = atomicAdd(&g_cursor[d], 1);
        g_csr[p] = s;
    }
}

// ---------------- tf32 tensor-core GEMM:  Y[m,:] = scale[m] * (A[m,:] @ B) ----
__device__ __forceinline__ uint32_t f2tf(float f) {
    uint32_t r;
    asm("cvt.rna.tf32.f32 %0, %1;" : "=r"(r) : "f"(f));
    return r;
}

__device__ __forceinline__ void mma_tf32(float* c, const uint32_t* a, const uint32_t* b) {
    asm volatile(
        "mma.sync.aligned.m16n8k8.row.col.f32.tf32.tf32.f32 "
        "{%0,%1,%2,%3}, {%4,%5,%6,%7}, {%8,%9}, {%0,%1,%2,%3};\n"
        : "+f"(c[0]), "+f"(c[1]), "+f"(c[2]), "+f"(c[3])
        : "r"(a[0]), "r"(a[1]), "r"(a[2]), "r"(a[3]),
          "r"(b[0]), "r"(b[1]));
}

#define BM 128
#define BN 64
#define BKT 32
// 256 threads = 8 warps in a 4(M) x 2(N) grid, each warp computes 32x32.
__global__ __launch_bounds__(256)
void gemm_tf32_scaled(const float* __restrict__ A, const float* __restrict__ B,
                      const float* __restrict__ scale, float* __restrict__ Y,
                      int M, int K) {
    __shared__ uint32_t As[BM][36];  // padded: 4*gid+tig -> conflict-free frag loads
    __shared__ uint32_t Bs[BKT][72]; // padded: 8*tig+gid -> conflict-free frag loads

    int tid  = threadIdx.x;
    int lane = tid & 31, warp = tid >> 5;
    int wm = warp >> 1, wn = warp & 1;
    int gid = lane >> 2, tig = lane & 3;
    int m0 = blockIdx.x * BM;
    int n0 = blockIdx.y * BN;

    float c[2][4][4] = {};

    for (int k0 = 0; k0 < K; k0 += BKT) {
        // A tile: 128x32 floats = 1024 float4, 4 per thread
        #pragma unroll
        for (int t = 0; t < 4; ++t) {
            int f4 = tid + t * 256;
            int r = f4 >> 3, cc = (f4 & 7) << 2;
            int gr = m0 + r;
            float4 v = make_float4(0.f, 0.f, 0.f, 0.f);
            if (gr < M) v = *(const float4*)(A + (size_t)gr * K + k0 + cc);
            As[r][cc + 0] = f2tf(v.x);
            As[r][cc + 1] = f2tf(v.y);
            As[r][cc + 2] = f2tf(v.z);
            As[r][cc + 3] = f2tf(v.w);
        }
        // B tile: 32x64 floats = 512 float4, 2 per thread
        #pragma unroll
        for (int t = 0; t < 2; ++t) {
            int f4 = tid + t * 256;
            int r = f4 >> 4, cc = (f4 & 15) << 2;
            float4 v = *(const float4*)(B + (size_t)(k0 + r) * DH + n0 + cc);
            Bs[r][cc + 0] = f2tf(v.x);
            Bs[r][cc + 1] = f2tf(v.y);
            Bs[r][cc + 2] = f2tf(v.z);
            Bs[r][cc + 3] = f2tf(v.w);
        }
        __syncthreads();

        #pragma unroll
        for (int kk = 0; kk < BKT; kk += 8) {
            uint32_t a[2][4], b[4][2];
            #pragma unroll
            for (int i = 0; i < 2; ++i) {
                int mrow = wm * 32 + i * 16;
                a[i][0] = As[mrow + gid][kk + tig];
                a[i][1] = As[mrow + gid + 8][kk + tig];
                a[i][2] = As[mrow + gid][kk + tig + 4];
                a[i][3] = As[mrow + gid + 8][kk + tig + 4];
            }
            #pragma unroll
            for (int j = 0; j < 4; ++j) {
                int ncol = wn * 32 + j * 8 + gid;
                b[j][0] = Bs[kk + tig][ncol];
                b[j][1] = Bs[kk + tig + 4][ncol];
            }
            #pragma unroll
            for (int i = 0; i < 2; ++i)
                #pragma unroll
                for (int j = 0; j < 4; ++j)
                    mma_tf32(c[i][j], a[i], b[j]);
        }
        __syncthreads();
    }

    // epilogue: scale rows by dinv[m]
    #pragma unroll
    for (int i = 0; i < 2; ++i) {
        int r0 = m0 + wm * 32 + i * 16 + gid;
        int r1 = r0 + 8;
        float s0 = (r0 < M) ? scale[r0] : 0.f;
        float s1 = (r1 < M) ? scale[r1] : 0.f;
        #pragma unroll
        for (int j = 0; j < 4; ++j) {
            int cb = n0 + wn * 32 + j * 8 + tig * 2;
            if (r0 < M) {
                Y[(size_t)r0 * DH + cb]     = s0 * c[i][j][0];
                Y[(size_t)r0 * DH + cb + 1] = s0 * c[i][j][1];
            }
            if (r1 < M) {
                Y[(size_t)r1 * DH + cb]     = s1 * c[i][j][2];
                Y[(size_t)r1 * DH + cb + 1] = s1 * c[i][j][3];
            }
        }
    }
}

// ---------------- warp-per-node gather aggregation ----------------------------
// out[node,:] = relu( dinv[node] * (sum_{src in in(node)} y[src,:] + y[node,:]) + bias )
__global__ __launch_bounds__(256)
void aggregate1_kernel(const float* __restrict__ y, const float* __restrict__ bias,
                       float* __restrict__ out, int n) {
    int gw   = (blockIdx.x * blockDim.x + threadIdx.x) >> 5;
    int lane = threadIdx.x & 31;
    if (gw >= n) return;
    int e0 = g_rowstart[gw], e1 = g_rowstart[gw + 1];

    float4 a0 = make_float4(0.f, 0.f, 0.f, 0.f);
    float4 a1 = make_float4(0.f, 0.f, 0.f, 0.f);

    int e = e0;
    for (; e + 4 <= e1; e += 4) {
        int s0 = g_csr[e], s1 = g_csr[e + 1], s2 = g_csr[e + 2], s3 = g_csr[e + 3];
        const float4* p0 = (const float4*)(y + (size_t)s0 * DH) + lane;
        const float4* p1 = (const float4*)(y + (size_t)s1 * DH) + lane;
        const float4* p2 = (const float4*)(y + (size_t)s2 * DH) + lane;
        const float4* p3 = (const float4*)(y + (size_t)s3 * DH) + lane;
        float4 u0 = p0[0], w0 = p0[32];
        float4 u1 = p1[0], w1 = p1[32];
        float4 u2 = p2[0], w2 = p2[32];
        float4 u3 = p3[0], w3 = p3[32];
        a0.x += u0.x + u1.x + u2.x + u3.x;  a0.y += u0.y + u1.y + u2.y + u3.y;
        a0.z += u0.z + u1.z + u2.z + u3.z;  a0.w += u0.w + u1.w + u2.w + u3.w;
        a1.x += w0.x + w1.x + w2.x + w3.x;  a1.y += w0.y + w1.y + w2.y + w3.y;
        a1.z += w0.z + w1.z + w2.z + w3.z;  a1.w += w0.w + w1.w + w2.w + w3.w;
    }
    for (; e < e1; ++e) {
        int s = g_csr[e];
        const float4* p = (const float4*)(y + (size_t)s * DH) + lane;
        float4 u = p[0], w = p[32];
        a0.x += u.x; a0.y += u.y; a0.z += u.z; a0.w += u.w;
        a1.x += w.x; a1.y += w.y; a1.z += w.z; a1.w += w.w;
    }
    // self loop
    {
        const float4* p = (const float4*)(y + (size_t)gw * DH) + lane;
        float4 u = p[0], w = p[32];
        a0.x += u.x; a0.y += u.y; a0.z += u.z; a0.w += u.w;
        a1.x += w.x; a1.y += w.y; a1.z += w.z; a1.w += w.w;
    }
    float dv = g_dinv[gw];
    float4 b0 = ((const float4*)bias)[lane];
    float4 b1 = ((const float4*)bias)[32 + lane];
    float4 r0, r1;
    r0.x = fmaxf(dv * a0.x + b0.x, 0.f); r0.y = fmaxf(dv * a0.y + b0.y, 0.f);
    r0.z = fmaxf(dv * a0.z + b0.z, 0.f); r0.w = fmaxf(dv * a0.w + b0.w, 0.f);
    r1.x = fmaxf(dv * a1.x + b1.x, 0.f); r1.y = fmaxf(dv * a1.y + b1.y, 0.f);
    r1.z = fmaxf(dv * a1.z + b1.z, 0.f); r1.w = fmaxf(dv * a1.w + b1.w, 0.f);
    float4* op = (float4*)(out + (size_t)gw * DH) + lane;
    op[0]  = r0;
    op[32] = r1;
}

// layer-2 aggregate fused with pool+FC: never materializes h2.
__global__ __launch_bounds__(256)
void aggregate2_pool_kernel(const float* __restrict__ y, const float* __restrict__ bias,
                            const float* __restrict__ wfc, const int* __restrict__ batch,
                            int n) {
    int gw   = (blockIdx.x * blockDim.x + threadIdx.x) >> 5;
    int lane = threadIdx.x & 31;
    if (gw >= n) return;
    int e0 = g_rowstart[gw], e1 = g_rowstart[gw + 1];

    float4 a0 = make_float4(0.f, 0.f, 0.f, 0.f);
    float4 a1 = make_float4(0.f, 0.f, 0.f, 0.f);

    int e = e0;
    for (; e + 4 <= e1; e += 4) {
        int s0 = g_csr[e], s1 = g_csr[e + 1], s2 = g_csr[e + 2], s3 = g_csr[e + 3];
        const float4* p0 = (const float4*)(y + (size_t)s0 * DH) + lane;
        const float4* p1 = (const float4*)(y + (size_t)s1 * DH) + lane;
        const float4* p2 = (const float4*)(y + (size_t)s2 * DH) + lane;
        const float4* p3 = (const float4*)(y + (size_t)s3 * DH) + lane;
        float4 u0 = p0[0], w0 = p0[32];
        float4 u1 = p1[0], w1 = p1[32];
        float4 u2 = p2[0], w2 = p2[32];
        float4 u3 = p3[0], w3 = p3[32];
        a0.x += u0.x + u1.x + u2.x + u3.x;  a0.y += u0.y + u1.y + u2.y + u3.y;
        a0.z += u0.z + u1.z + u2.z + u3.z;  a0.w += u0.w + u1.w + u2.w + u3.w;
        a1.x += w0.x + w1.x + w2.x + w3.x;  a1.y += w0.y + w1.y + w2.y + w3.y;
        a1.z += w0.z + w1.z + w2.z + w3.z;  a1.w += w0.w + w1.w + w2.w + w3.w;
    }
    for (; e < e1; ++e) {
        int s = g_csr[e];
        const float4* p = (const float4*)(y + (size_t)s * DH) + lane;
        float4 u = p[0], w = p[32];
        a0.x += u.x; a0.y += u.y; a0.z += u.z; a0.w += u.w;
        a1.x += w.x; a1.y += w.y; a1.z += w.z; a1.w += w.w;
    }
    {
        const float4* p = (const float4*)(y + (size_t)gw * DH) + lane;
        float4 u = p[0], w = p[32];
        a0.x += u.x; a0.y += u.y; a0.z += u.z; a0.w += u.w;
        a1.x += w.x; a1.y += w.y; a1.z += w.z; a1.w += w.w;
    }
    float dv = g_dinv[gw];
    float4 b0 = ((const float4*)bias)[lane];
    float4 b1 = ((const float4*)bias)[32 + lane];
    float4 f0 = ((const float4*)wfc)[lane];
    float4 f1 = ((const float4*)wfc)[32 + lane];

    float h;
    float dot = 0.f;
    h = fmaxf(dv * a0.x + b0.x, 0.f); dot += h * f0.x;
    h = fmaxf(dv * a0.y + b0.y, 0.f); dot += h * f0.y;
    h = fmaxf(dv * a0.z + b0.z, 0.f); dot += h * f0.z;
    h = fmaxf(dv * a0.w + b0.w, 0.f); dot += h * f0.w;
    h = fmaxf(dv * a1.x + b1.x, 0.f); dot += h * f1.x;
    h = fmaxf(dv * a1.y + b1.y, 0.f); dot += h * f1.y;
    h = fmaxf(dv * a1.z + b1.z, 0.f); dot += h * f1.z;
    h = fmaxf(dv * a1.w + b1.w, 0.f); dot += h * f1.w;

    #pragma unroll
    for (int off = 16; off > 0; off >>= 1)
        dot += __shfl_xor_sync(0xffffffffu, dot, off);
    if (lane == 0)
        atomicAdd(&g_gsum[batch[gw]], dot);
}

__global__ void finalize_kernel(float* __restrict__ out, const float* __restrict__ bfc) {
    int g = threadIdx.x;
    if (g < NGR)
        out[g] = g_gsum[g] / fmaxf((float)g_cnt[g], 1.0f) + bfc[0];
}

// ---------------- launch ------------------------------------------------------
extern "C" void kernel_launch(void* const* d_in, const int* in_sizes, int n_in,
                              void* d_out, int out_size) {
    const float* x     = (const float*)d_in[0];
    const int*   ei    = (const int*)  d_in[1];
    const int*   batch = (const int*)  d_in[2];
    const float* W1    = (const float*)d_in[3];
    const float* b1    = (const float*)d_in[4];
    const float* W2    = (const float*)d_in[5];
    const float* b2    = (const float*)d_in[6];
    const float* wfc   = (const float*)d_in[7];
    const float* bfc   = (const float*)d_in[8];
    float* out = (float*)d_out;

    int n = in_sizes[0] / DIN;   // 20000
    int e = in_sizes[1] / 2;     // 320000

    float* yptr = nullptr;
    float* hptr = nullptr;
    cudaGetSymbolAddress((void**)&yptr, g_y);
    cudaGetSymbolAddress((void**)&hptr, g_h);

    int tz = (n + 255) / 256;
    zero_kernel<<<tz, 256>>>(n);

    int th = (e + 255) / 256;
    hist_kernel<<<th, 256>>>(ei, batch, n, e);

    scan_kernel<<<1, 1024>>>(n);

    fill_kernel<<<th, 256>>>(ei, e);

    float* dinvptr = nullptr;
    cudaGetSymbolAddress((void**)&dinvptr, g_dinv);

    dim3 ggrid((n + BM - 1) / BM, DH / BN);
    gemm_tf32_scaled<<<ggrid, 256>>>(x, W1, dinvptr, yptr, n, DIN);

    int ta = ((n * 32) + 255) / 256;
    aggregate1_kernel<<<ta, 256>>>(yptr, b1, hptr, n);

    gemm_tf32_scaled<<<ggrid, 256>>>(hptr, W2, dinvptr, yptr, n, DH);

    aggregate2_pool_kernel<<<ta, 256>>>(yptr, b2, wfc, batch, n);

    finalize_kernel<<<1, NGR>>>(out, bfc);
}